// round 16
// baseline (speedup 1.0000x reference)
#include <cuda_runtime.h>
#include <cstdint>

// ---------------------------------------------------------------------------
// SE3Net (all l=0): K(r) is a scalar function of distance, zero for r>=4.5.
// R15 (59.5us) with ONE change: MLP j-split 4 -> 8 ways at CONSTANT thread
// count (400). Thread = (j-octant q, column-pair c2): 13 LDG.64 + 13 LDS.128
// per thread per layer (halved LSU ops, same warps — the unconfounded R14).
// Overlap (fork/join streams), conv kernel, flags: R15 verbatim.
// ---------------------------------------------------------------------------

#define NPTS    32
#define OCP     52          // table row stride (floats)
#define CIN     23
#define FSTR    28          // feature row stride (floats)
#define NB      286
#define BATCH   4
#define HDIM    100
#define CPAD    104         // padded h rows (pads stay zero)
#define NLAYERS 49
#define RMAX    4.5f
#define DELTA   (RMAX / (float)(NPTS - 1))
#define INV_DELTA ((float)(NPTS - 1) / RMAX)

#define TM 4
#define GRID_MLP (NPTS / TM)        // 8
#define QD 8                        // j-octant split
#define JPO 13                      // j per octant (8*13 = 104)
#define CP2 (HDIM / 2)              // 50 column pairs
#define MLP_THREADS (QD * CP2)      // 400

#define ATOMS_PB 8
#define CONV_THREADS 256
#define NBXC ((NB + ATOMS_PB - 1) / ATOMS_PB)   // 36
#define JSPLIT 2
#define BLOCKS_PER_BATCH (NBXC * JSPLIT)        // 72

typedef unsigned long long ull;

__device__ __align__(16) float g_table[NPTS * OCP];
__device__ float g_rows[BATCH * NB * 2];
__device__ int   g_ctr[BATCH];
__device__ int   g_flag;        // table ready (release/acquire)
__device__ int   g_mlp_done;
__device__ int   g_done;

__device__ __forceinline__ ull ffma2(ull a, ull b, ull c) {
    ull d;
    asm("fma.rn.f32x2 %0, %1, %2, %3;" : "=l"(d) : "l"(a), "l"(b), "l"(c));
    return d;
}
__device__ __forceinline__ ull add2(ull a, ull b) {
    ull d;
    asm("add.rn.f32x2 %0, %1, %2;" : "=l"(d) : "l"(a), "l"(b));
    return d;
}
__device__ __forceinline__ ull pack2(float lo, float hi) {
    ull d;
    asm("mov.b64 %0, {%1, %2};" : "=l"(d) : "f"(lo), "f"(hi));
    return d;
}
__device__ __forceinline__ float2 unpack2(ull v) {
    float lo, hi;
    asm("mov.b64 {%0, %1}, %2;" : "=f"(lo), "=f"(hi) : "l"(v));
    return make_float2(lo, hi);
}
__device__ __forceinline__ float bump(float x) {
    float ax = fabsf(x);
    if (ax >= 1.0f) return 0.0f;
    float c = cosf(1.5707963267948966f * x);
    return c * c;
}

// ---------------------------------------------------------------------------
// Kernel 1: grid MLP. (q, c2) threads, float2 register weights, 8-way combine.
// ---------------------------------------------------------------------------
__global__ void __launch_bounds__(MLP_THREADS) mlp_table_kernel(
    const float* __restrict__ w_in,    // [3,100]
    const float* __restrict__ w_h,     // [49,100,100]
    const float* __restrict__ w_out)   // [100,46]
{
    __shared__ __align__(16) ull h2[2][CPAD][2];    // [buf][j][rowpair]
    __shared__ __align__(16) ull part[QD][CP2][5];  // [q][c2][4 used + pad]

    const int tid = threadIdx.x;
    const int m0  = blockIdx.x * TM;
    const int q   = tid / CP2;         // 0..7
    const int c2  = tid % CP2;         // 0..49
    const int j0  = q * JPO;

    float2 wcur[JPO], wnxt[JPO];
    // prologue: layer-0 weights (LDG.64, coalesced in c2).
    // j >= 100 reads are clamped to row 99 (valid) and multiplied by the
    // zero h-pads, so they contribute exactly 0.
    {
        const float* base = w_h + 2 * c2;
#pragma unroll
        for (int jj = 0; jj < JPO; jj++) {
            int j = j0 + jj;
            int je = (j < HDIM) ? j : (HDIM - 1);
            wcur[jj] = *reinterpret_cast<const float2*>(base + je * HDIM);
        }
    }

    // zero the h pads (rows 100..103) of BOTH buffers, once
    if (tid < 2 * (CPAD - HDIM) * 2) {          // 16 threads
        int b = tid >> 3, r = (tid >> 1) & 3, p = tid & 1;
        h2[b][HDIM + r][p] = 0ULL;
    }

    // ---- layer 0: basis -> h (tid<100 covers each column once) ----
    if (tid < HDIM) {
        const float inv_sqrt3 = 0.57735026918962576f;
        float wi0 = w_in[tid], wi1 = w_in[HDIM + tid], wi2 = w_in[2 * HDIM + tid];
        float v[TM];
#pragma unroll
        for (int r = 0; r < TM; r++) {
            float rr = (float)(m0 + r) * DELTA;
            float b0 = bump(rr * (1.0f / 1.5f));
            float b1 = bump((rr - 1.5f) * (1.0f / 1.5f));
            float b2 = bump((rr - 3.0f) * (1.0f / 1.5f));
            float a = (b0 * wi0 + b1 * wi1 + b2 * wi2) * inv_sqrt3;
            v[r] = fmaxf(a, 0.0f);
        }
        h2[0][tid][0] = pack2(v[0], v[1]);
        h2[0][tid][1] = pack2(v[2], v[3]);
    }
    __syncthreads();

    int cur = 0;
#pragma unroll 1
    for (int l = 0; l < NLAYERS; l++) {
        // prefetch next layer's weights (hidden behind compute)
        if (l + 1 < NLAYERS) {
            const float* base = w_h + (size_t)(l + 1) * (HDIM * HDIM) + 2 * c2;
#pragma unroll
            for (int jj = 0; jj < JPO; jj++) {
                int j = j0 + jj;
                int je = (j < HDIM) ? j : (HDIM - 1);
                wnxt[jj] = *reinterpret_cast<const float2*>(base + je * HDIM);
            }
        }

        // 13 j-steps: 1 LDS.128 h + 4 FFMA2 (2 cols x 2 rowpairs)
        ull a00 = 0, a01 = 0, a10 = 0, a11 = 0;
#pragma unroll
        for (int jj = 0; jj < JPO; jj++) {
            ulonglong2 hv = *reinterpret_cast<const ulonglong2*>(
                &h2[cur][j0 + jj][0]);
            float2 w2 = wcur[jj];
            ull pw0 = pack2(w2.x, w2.x);
            ull pw1 = pack2(w2.y, w2.y);
            a00 = ffma2(hv.x, pw0, a00);
            a01 = ffma2(hv.y, pw0, a01);
            a10 = ffma2(hv.x, pw1, a10);
            a11 = ffma2(hv.y, pw1, a11);
        }
        part[q][c2][0] = a00;   // col 2*c2,   rowpair 0
        part[q][c2][1] = a01;   // col 2*c2,   rowpair 1
        part[q][c2][2] = a10;   // col 2*c2+1, rowpair 0
        part[q][c2][3] = a11;   // col 2*c2+1, rowpair 1
        __syncthreads();

        if (tid < HDIM) {
            int cc = tid >> 1, k = (tid & 1) * 2;
            ull s0 = part[0][cc][k + 0];
            ull s1 = part[0][cc][k + 1];
#pragma unroll
            for (int qq = 1; qq < QD; qq++) {
                s0 = add2(s0, part[qq][cc][k + 0]);
                s1 = add2(s1, part[qq][cc][k + 1]);
            }
            float2 v0 = unpack2(s0), v1 = unpack2(s1);
            h2[cur ^ 1][tid][0] = pack2(fmaxf(v0.x * 0.1f, 0.0f),
                                        fmaxf(v0.y * 0.1f, 0.0f));
            h2[cur ^ 1][tid][1] = pack2(fmaxf(v1.x * 0.1f, 0.0f),
                                        fmaxf(v1.y * 0.1f, 0.0f));
        }
        __syncthreads();

        if (l + 1 < NLAYERS) {
#pragma unroll
            for (int jj = 0; jj < JPO; jj++) wcur[jj] = wnxt[jj];
        }
        cur ^= 1;
    }

    // ---- output layer: 46 cols x 4 rows = 184 threads; zero row pads ----
    if (tid < 2 * CIN * TM) {
        int o = tid % (2 * CIN);
        int r = tid / (2 * CIN);
        const float* hp = reinterpret_cast<const float*>(&h2[cur][0][0])
                          + (r >> 1) * 2 + (r & 1);
        float acc = 0.0f;
#pragma unroll 4
        for (int j = 0; j < HDIM; j++)
            acc = fmaf(hp[j * 4], w_out[j * (2 * CIN) + o], acc);
        const float SCALE = 0.1f * 0.28209479177387814f * 0.5f;
        int co = o % CIN, oo = o / CIN;
        g_table[(m0 + r) * OCP + co * 2 + oo] = acc * SCALE;
    }
    for (int z = tid; z < TM * (OCP - 2 * CIN); z += MLP_THREADS) {
        int r = z / (OCP - 2 * CIN);
        int pos = 2 * CIN + z % (OCP - 2 * CIN);
        g_table[(m0 + r) * OCP + pos] = 0.0f;
    }

    // ---- release: last MLP block publishes the table ----
    __threadfence();
    __syncthreads();
    if (tid == 0) {
        int prev = atomicAdd(&g_mlp_done, 1);
        if (prev == GRID_MLP - 1) atomicExch(&g_flag, 1);
    }
}

// ---------------------------------------------------------------------------
// Kernel 2: pairwise conv gated on the table flag. (R15 verbatim)
// ---------------------------------------------------------------------------
__global__ void __launch_bounds__(CONV_THREADS) conv_kernel(
    const float* __restrict__ features,   // [B,N,23]
    const float* __restrict__ geometry,   // [B,N,3]
    const float* __restrict__ lin_w,      // [2]
    const float* __restrict__ lin_b,      // [1]
    float* __restrict__ out)              // [B]
{
    extern __shared__ __align__(16) float cs[];
    float* table_s = cs;                            // NPTS*OCP  (1664 f)
    float* feat_s  = cs + NPTS * OCP;               // NB*FSTR   (8008 f)
    float* geo_s   = feat_s + NB * FSTR;            // NB*4      (1144 f)
    __shared__ float red0[CONV_THREADS];
    __shared__ float red1[CONV_THREADS];
    __shared__ int last_flag;

    const int tid = threadIdx.x;
    const int wrp = tid >> 5;
    const int ln  = tid & 31;
    const int b = blockIdx.z;
    const int js = blockIdx.y;                      // j-split 0..1

    // ---- stage features (div-free, warp-per-row) + geometry NOW ----
    const float* fb = features + (size_t)b * NB * CIN;
    for (int jr = wrp; jr < NB; jr += CONV_THREADS / 32) {
        if (ln < FSTR)
            feat_s[jr * FSTR + ln] = (ln < CIN) ? fb[jr * CIN + ln] : 0.0f;
    }
    const float* gb = geometry + (size_t)b * NB * 3;
    for (int k = tid; k < NB * 4; k += CONV_THREADS) {
        int j = k >> 2, d = k & 3;
        geo_s[k] = (d < 3) ? gb[j * 3 + d] : 0.0f;
    }

    // ---- wait for the table (released by mlp kernel on parallel branch) ----
    if (tid == 0) {
        int v;
        do {
            asm volatile("ld.acquire.gpu.global.s32 %0, [%1];"
                         : "=r"(v) : "l"(&g_flag) : "memory");
            if (!v) __nanosleep(200);
        } while (!v);
    }
    __syncthreads();

    // ---- copy table (416 float4) ----
    for (int k = tid; k < (NPTS * OCP) / 4; k += CONV_THREADS)
        reinterpret_cast<float4*>(table_s)[k] =
            reinterpret_cast<const float4*>(g_table)[k];
    __syncthreads();

    const int i = blockIdx.x * ATOMS_PB + wrp;
    const bool valid = (i < NB);
    float gx = 0.f, gy = 0.f, gz = 0.f;
    if (valid) { gx = geo_s[i * 4]; gy = geo_s[i * 4 + 1]; gz = geo_s[i * 4 + 2]; }

    const int jbeg = js * (NB / JSPLIT);
    const int jend = jbeg + (NB / JSPLIT);

    ull acc = 0ULL;
    for (int j = jbeg + ln; j < jend; j += 32) {
        float4 g4 = *reinterpret_cast<const float4*>(geo_s + j * 4);
        float dx = g4.x - gx, dy = g4.y - gy, dz = g4.z - gz;
        float r = sqrtf(fmaf(dx, dx, fmaf(dy, dy, fmaf(dz, dz, 1e-12f))));
        int u = __float2int_rn(r * INV_DELTA);
        if (valid && u < NPTS) {
            const ulonglong2* __restrict__ T =
                reinterpret_cast<const ulonglong2*>(table_s + u * OCP);
            const float4* __restrict__ f4 =
                reinterpret_cast<const float4*>(feat_s + j * FSTR);
            ull d0 = 0ULL, d1 = 0ULL;
#pragma unroll
            for (int k = 0; k < 6; k++) {
                float4 f = f4[k];
                ulonglong2 t0 = T[2 * k];
                ulonglong2 t1 = T[2 * k + 1];
                d0 = ffma2(t0.x, pack2(f.x, f.x), d0);
                d1 = ffma2(t0.y, pack2(f.y, f.y), d1);
                d0 = ffma2(t1.x, pack2(f.z, f.z), d0);
                d1 = ffma2(t1.y, pack2(f.w, f.w), d1);
            }
            acc = add2(acc, add2(d0, d1));
        }
    }

    float2 av = unpack2(acc);
    float acc0 = av.x, acc1 = av.y;
#pragma unroll
    for (int off = 16; off > 0; off >>= 1) {
        acc0 += __shfl_xor_sync(0xffffffffu, acc0, off);
        acc1 += __shfl_xor_sync(0xffffffffu, acc1, off);
    }
    if (ln == 0 && valid) {
        // exactly 2 addends per row (JSPLIT=2): commutative -> deterministic
        atomicAdd(&g_rows[(b * NB + i) * 2 + 0], acc0);
        atomicAdd(&g_rows[(b * NB + i) * 2 + 1], acc1);
    }

    // ---- fused epilogue: last block of this batch does relu+mean+linear ----
    __threadfence();
    __syncthreads();
    if (tid == 0)
        last_flag = (atomicAdd(&g_ctr[b], 1) == BLOCKS_PER_BATCH - 1) ? 1 : 0;
    __syncthreads();
    if (last_flag) {
        __threadfence();
        float s0 = 0.f, s1 = 0.f;
        for (int k = tid; k < NB; k += CONV_THREADS) {
            s0 += fmaxf(g_rows[(b * NB + k) * 2 + 0], 0.0f);
            s1 += fmaxf(g_rows[(b * NB + k) * 2 + 1], 0.0f);
            g_rows[(b * NB + k) * 2 + 0] = 0.0f;    // reset for next replay
            g_rows[(b * NB + k) * 2 + 1] = 0.0f;
        }
        red0[tid] = s0; red1[tid] = s1;
        __syncthreads();
#pragma unroll
        for (int s = CONV_THREADS / 2; s > 0; s >>= 1) {
            if (tid < s) { red0[tid] += red0[tid + s]; red1[tid] += red1[tid + s]; }
            __syncthreads();
        }
        if (tid == 0) {
            out[b] = (red0[0] * lin_w[0] + red1[0] * lin_w[1])
                     * (1.0f / (float)NB) + lin_b[0];
            g_ctr[b] = 0;                           // reset for next replay
            int p = atomicAdd(&g_done, 1);
            if (p == BATCH - 1) {                   // final replay reset
                g_flag = 0;
                g_mlp_done = 0;
                g_done = 0;
            }
        }
    }
}

// ---------------------------------------------------------------------------
extern "C" void kernel_launch(void* const* d_in, const int* in_sizes, int n_in,
                              void* d_out, int out_size) {
    int o = 0;
    if (n_in >= 4 && in_sizes[2] == 1) o = 1;   // num_atoms scalar present

    const float* features = (const float*)d_in[0];
    const float* geometry = (const float*)d_in[1];
    const float* w_in     = (const float*)d_in[2 + o];
    const float* w_h      = (const float*)d_in[3 + o];
    const float* w_out    = (const float*)d_in[4 + o];
    const float* lin_w    = (const float*)d_in[5 + o];
    const float* lin_b    = (const float*)d_in[6 + o];

    // One-time setup on the (uncaptured) correctness call.
    static cudaStream_t s_side = nullptr;
    static cudaEvent_t  s_fork = nullptr, s_join = nullptr;
    if (s_side == nullptr) {
        cudaStreamCreateWithFlags(&s_side, cudaStreamNonBlocking);
        cudaEventCreateWithFlags(&s_fork, cudaEventDisableTiming);
        cudaEventCreateWithFlags(&s_join, cudaEventDisableTiming);
    }

    const int conv_smem = (NPTS * OCP + NB * FSTR + NB * 4) * (int)sizeof(float);
    cudaFuncSetAttribute(conv_kernel,
                         cudaFuncAttributeMaxDynamicSharedMemorySize, conv_smem);

    // Fork: mlp runs on the side branch, conv on the main branch, in parallel.
    cudaEventRecord(s_fork, 0);
    cudaStreamWaitEvent(s_side, s_fork, 0);

    mlp_table_kernel<<<GRID_MLP, MLP_THREADS, 0, s_side>>>(w_in, w_h, w_out);
    cudaEventRecord(s_join, s_side);

    conv_kernel<<<dim3(NBXC, JSPLIT, BATCH), CONV_THREADS, conv_smem>>>(
        features, geometry, lin_w, lin_b, (float*)d_out);

    // Join: main branch completes only after both kernels.
    cudaStreamWaitEvent(0, s_join, 0);
}